// round 15
// baseline (speedup 1.0000x reference)
#include <cuda_runtime.h>
#include <cuda_fp16.h>
#include <cstdint>

// Problem constants
#define B_    256
#define N_    128
#define EB_   5
#define NA_   64
#define DIM_  512
#define NIT_  3
#define MROWS (B_ * N_)
#define LSZ   (DIM_ * DIM_)
#define WSZ   (NIT_ * LSZ + DIM_ * NA_)

// Scratch (static device globals)
__device__ __align__(128) float  g_hT[B_ * DIM_ * N_];   // [B][512][128]
__device__ __align__(128) float  g_t [B_ * N_ * DIM_];   // [B][128][512]
__device__ __align__(128) __half g_wh[WSZ];              // wT pre-split hi
__device__ __align__(128) __half g_wl[WSZ];
__device__ __align__(128) __half g_ah[B_ * N_ * N_];     // M = Σedges + I
__device__ __align__(128) __half g_al[B_ * N_ * N_];
__device__ __align__(128) float  g_rs[MROWS];            // rowsums of M
__device__ __align__(128) float  g_nodeT[B_ * NA_ * N_]; // [B][64][128]
__device__ __align__(128) float  g_q[B_ * N_ * NA_];     // [B][128][64]
__device__ __align__(128) __half g_we1h[DIM_ * NA_];     // (We@W1)^T split
__device__ __align__(128) __half g_we1l[DIM_ * NA_];
__device__ __align__(128) float  g_we1p[8 * DIM_ * NA_];
__device__ __align__(128) float  g_be1[DIM_];

// ---------------------------------------------------------------------------
// helpers
// ---------------------------------------------------------------------------
__device__ __forceinline__ void split2u(float a0, float a1, uint32_t& hi, uint32_t& lo) {
    __half2 h = __floats2half2_rn(a0, a1);
    float2  f = __half22float2(h);
    __half2 l = __floats2half2_rn(a0 - f.x, a1 - f.y);
    hi = *reinterpret_cast<uint32_t*>(&h);
    lo = *reinterpret_cast<uint32_t*>(&l);
}
__device__ __forceinline__ uint32_t smem_u32(const void* p) {
    uint32_t a;
    asm("{ .reg .u64 t; cvta.to.shared.u64 t, %1; cvt.u32.u64 %0, t; }" : "=r"(a) : "l"(p));
    return a;
}
__device__ __forceinline__ void cpasync16(uint32_t s, const void* g) {
    asm volatile("cp.async.cg.shared.global [%0], [%1], 16;" :: "r"(s), "l"(g));
}
#define CP_COMMIT() asm volatile("cp.async.commit_group;" ::: "memory")
#define CP_WAIT(n)  asm volatile("cp.async.wait_group %0;" :: "n"(n) : "memory")

#define LDSM4(r, addr) \
    asm volatile("ldmatrix.sync.aligned.m8n8.x4.shared.b16 {%0,%1,%2,%3}, [%4];" \
        : "=r"((r)[0]), "=r"((r)[1]), "=r"((r)[2]), "=r"((r)[3]) : "r"(addr))

__device__ __forceinline__ void mma16816(float* c, const uint32_t* a,
                                         uint32_t b0, uint32_t b1) {
    asm volatile(
        "mma.sync.aligned.m16n8k16.row.col.f32.f16.f16.f32 "
        "{%0,%1,%2,%3}, {%4,%5,%6,%7}, {%8,%9}, {%0,%1,%2,%3};"
        : "+f"(c[0]), "+f"(c[1]), "+f"(c[2]), "+f"(c[3])
        : "r"(a[0]), "r"(a[1]), "r"(a[2]), "r"(a[3]), "r"(b0), "r"(b1));
}

// swizzled byte offset inside one [rows][64B] tile
__device__ __forceinline__ uint32_t swz(int r, int kh) {
    return (uint32_t)(r * 64) + (uint32_t)((kh ^ ((r >> 1) & 3)) << 4);
}

// ---------------------------------------------------------------------------
// Prep kernels (unchanged from round 14)
// ---------------------------------------------------------------------------
__global__ void asum_split_kernel(const float* __restrict__ adj,
                                  __half* __restrict__ ah, __half* __restrict__ al,
                                  float* __restrict__ rs) {
    int g = blockIdx.x * 256 + threadIdx.x;
    const float4* p = (const float4*)adj + (long long)g * 5;
    float4 f0 = p[0], f1 = p[1], f2 = p[2], f3 = p[3], f4 = p[4];
    float4 o;
    o.x = (f0.y + f0.z) + (f0.w + f1.x);
    o.y = (f1.z + f1.w) + (f2.x + f2.y);
    o.z = (f2.w + f3.x) + (f3.y + f3.z);
    o.w = (f4.x + f4.y) + (f4.z + f4.w);
    int i = g * 4;
    #pragma unroll
    for (int j = 0; j < 4; j++) {
        int nm = (i + j) & (N_ * N_ - 1);
        if ((nm >> 7) == (nm & 127)) (&o.x)[j] += 1.0f;
    }
    uint32_t h0, l0, h1, l1;
    split2u(o.x, o.y, h0, l0);
    split2u(o.z, o.w, h1, l1);
    ((uint2*)ah)[g] = make_uint2(h0, h1);
    ((uint2*)al)[g] = make_uint2(l0, l1);
    float s = (o.x + o.y) + (o.z + o.w);
    #pragma unroll
    for (int off = 16; off; off >>= 1) s += __shfl_xor_sync(0xFFFFFFFFu, s, off);
    if ((threadIdx.x & 31) == 0) rs[g >> 5] = s;
}

__global__ void wsplit_kernel(const float* __restrict__ W_layers,
                              const float* __restrict__ W_embed,
                              __half* __restrict__ wh, __half* __restrict__ wl) {
    int i = blockIdx.x * 256 + threadIdx.x;
    float v;
    if (i < NIT_ * LSZ) {
        int l = i / LSZ, j = i % LSZ;
        int c = j / DIM_, r = j % DIM_;
        v = W_layers[l * LSZ + r * DIM_ + c];
    } else {
        int j = i - NIT_ * LSZ;
        int c = j / NA_, r = j % NA_;
        v = W_embed[r * DIM_ + c];
    }
    __half h = __float2half_rn(v);
    wh[i] = h;
    wl[i] = __float2half_rn(v - __half2float(h));
}

__global__ void nodet_kernel(const float* __restrict__ node, float* __restrict__ nodeT) {
    int i = blockIdx.x * 256 + threadIdx.x;
    int b = i >> 13, j = i & 8191, na = j >> 7, m = j & 127;
    nodeT[i] = node[(b << 13) + (m << 6) + na];
}

__global__ void we1part_kernel(const float* __restrict__ We, const float* __restrict__ W1,
                               float* __restrict__ we1p) {
    int blk = blockIdx.x;
    int ks  = blk >> 7;
    int i   = (blk & 127) * 256 + threadIdx.x;
    int na = i >> 9, d = i & 511;
    float s = 0.0f;
    const float* wer = We + na * DIM_ + ks * 64;
    const float* w1r = W1 + (long long)(ks * 64) * DIM_ + d;
    #pragma unroll 8
    for (int k = 0; k < 64; k++) s += wer[k] * w1r[(long long)k * DIM_];
    we1p[ks * (DIM_ * NA_) + i] = s;
}

__global__ void we1red_kernel(const float* __restrict__ we1p,
                              __half* __restrict__ weh, __half* __restrict__ wel) {
    int i = blockIdx.x * 256 + threadIdx.x;
    float s = 0.0f;
    #pragma unroll
    for (int ks = 0; ks < 8; ks++) s += we1p[ks * (DIM_ * NA_) + i];
    int na = i >> 9, d = i & 511;
    __half h = __float2half_rn(s);
    weh[d * NA_ + na] = h;
    wel[d * NA_ + na] = __float2half_rn(s - __half2float(h));
}

__global__ void be1_kernel(const float* __restrict__ be, const float* __restrict__ W1,
                           float* __restrict__ be1) {
    int d = blockIdx.x * 8 + (threadIdx.x >> 5);
    int lane = threadIdx.x & 31;
    float s = 0.0f;
    #pragma unroll
    for (int j = 0; j < 16; j++) {
        int k = lane + 32 * j;
        s += be[k] * W1[(long long)k * DIM_ + d];
    }
    #pragma unroll
    for (int off = 16; off; off >>= 1) s += __shfl_xor_sync(0xFFFFFFFFu, s, off);
    if (lane == 0) be1[d] = s;
}

// ---------------------------------------------------------------------------
// 3xFP16-split tensor GEMM, 128-thread CTAs (4 CTAs/SM target):
//   D tile 64 x NTILE of A[M,K] @ B[N,K]^T.
//   A pre-split half hi/lo (cp.async double buffer); B fp32 split in-kernel
//   (two 16-float waves pipelined under the k16 slices); fp32 D output.
//   v = acc*outScale + bias[row] + rv[row]*cv[col]; optional relu.
// 4 warps = 2m x 2n of 32x(NTILE/2) warp tiles.
// Smem/buf: AH 4KB | AL 4KB | BH 8KB | BL 8KB = 24KB; x2 buf = 48KB.
// ---------------------------------------------------------------------------
#define OFF_AH 0
#define OFF_AL 4096
#define OFF_BH 8192
#define OFF_BL 16384
#define BUF_BYTES  24576
#define SMEM_BYTES 49152

template<int NTG>
__global__ __launch_bounds__(128, 4)
void tgemm(const __half* __restrict__ Ah, const __half* __restrict__ Al, long long aBS,
           const float* __restrict__ Bm, long long bBS,
           float* __restrict__ D, long long dBS,
           const float* __restrict__ bias,
           int K, int Nglob, int ntiles, int relu,
           float bScale, float outScale,
           const float* __restrict__ rv, const float* __restrict__ cv)
{
    extern __shared__ char smem[];
    const uint32_t sb = smem_u32(smem);
    constexpr int NTILE = 32 * NTG;

    const int tid  = threadIdx.x;
    const int lane = tid & 31;
    const int warp = tid >> 5;             // 0..3
    const int mtb  = blockIdx.x / ntiles;
    const int ntb  = blockIdx.x % ntiles;
    const int wm   = (warp >> 1) * 32;     // 0,32
    const int wn   = (warp & 1) * (NTILE / 2);

    const __half* Aph = Ah + aBS * blockIdx.y + (long long)mtb * 64 * K;
    const __half* Apl = Al + aBS * blockIdx.y + (long long)mtb * 64 * K;
    const float*  Bp  = Bm + bBS * blockIdx.y + (long long)ntb * NTILE * K;

    // ---- A loader: row ar = tid>>1 (0..63), 32B half-row ha ----
    const int ar = tid >> 1;
    const int ha = tid & 1;
    const uint32_t aso0 = swz(ar, 2 * ha);
    const uint32_t aso1 = swz(ar, 2 * ha + 1);
    const long long ago = (long long)ar * K + ha * 16;

    // ---- B loader: wave0 row rb (0..63+), wave1 row rb+64 (NTG==4) ----
    const int rb = tid >> 1;
    const int hb = tid & 1;
    const uint32_t bso0a = swz(rb, 2 * hb),      bso0b = swz(rb, 2 * hb + 1);
    const uint32_t bso1a = swz(rb + 64, 2 * hb), bso1b = swz(rb + 64, 2 * hb + 1);
    const long long bgo0 = (long long)rb * K + hb * 16;
    const long long bgo1 = (long long)(rb + 64) * K + hb * 16;

    // ---- ldmatrix addresses ----
    const int lane8 = lane & 7;
    const int rA0   = ((lane >> 3) & 1) * 8 + lane8;
    const int khA   = lane >> 4;
    const int rB0   = ((lane >> 4) & 1) * 8 + lane8;
    const int khB   = (lane >> 3) & 1;

    uint32_t aAddr[2][2], bAddr[NTG][2];
    #pragma unroll
    for (int mt = 0; mt < 2; mt++) {
        const int r = wm + mt * 16 + rA0;
        #pragma unroll
        for (int s = 0; s < 2; s++) aAddr[mt][s] = swz(r, s * 2 + khA);
    }
    #pragma unroll
    for (int nt = 0; nt < NTG; nt++) {
        const int r = wn + nt * 16 + rB0;
        #pragma unroll
        for (int s = 0; s < 2; s++) bAddr[nt][s] = swz(r, s * 2 + khB);
    }

    float acc[2][2 * NTG][4];
    #pragma unroll
    for (int i = 0; i < 2; i++)
        #pragma unroll
        for (int j = 0; j < 2 * NTG; j++)
            #pragma unroll
            for (int q = 0; q < 4; q++) acc[i][j][q] = 0.0f;

    const int C = K >> 5;
    int buf = 0;
    float4 fr0, fr1, fr2, fr3;             // 16-float B wave staging

    auto issueA = [&](uint32_t bo, int g) {
        cpasync16(sb + bo + OFF_AH + aso0, Aph + ago + g);
        cpasync16(sb + bo + OFF_AH + aso1, Aph + ago + g + 8);
        cpasync16(sb + bo + OFF_AL + aso0, Apl + ago + g);
        cpasync16(sb + bo + OFF_AL + aso1, Apl + ago + g + 8);
        CP_COMMIT();
    };
    auto loadB = [&](int w, int g) {
        const float* p = Bp + (w ? bgo1 : bgo0) + g;
        fr0 = *(const float4*)(p);
        fr1 = *(const float4*)(p + 4);
        fr2 = *(const float4*)(p + 8);
        fr3 = *(const float4*)(p + 12);
    };
    auto stsB = [&](int w, uint32_t bo) {
        uint32_t h0,h1,h2,h3,h4,h5,h6,h7, l0,l1,l2,l3,l4,l5,l6,l7;
        split2u(fr0.x * bScale, fr0.y * bScale, h0, l0);
        split2u(fr0.z * bScale, fr0.w * bScale, h1, l1);
        split2u(fr1.x * bScale, fr1.y * bScale, h2, l2);
        split2u(fr1.z * bScale, fr1.w * bScale, h3, l3);
        split2u(fr2.x * bScale, fr2.y * bScale, h4, l4);
        split2u(fr2.z * bScale, fr2.w * bScale, h5, l5);
        split2u(fr3.x * bScale, fr3.y * bScale, h6, l6);
        split2u(fr3.z * bScale, fr3.w * bScale, h7, l7);
        const uint32_t sa = w ? bso1a : bso0a;
        const uint32_t sbo = w ? bso1b : bso0b;
        *(uint4*)(smem + bo + OFF_BH + sa)  = make_uint4(h0, h1, h2, h3);
        *(uint4*)(smem + bo + OFF_BH + sbo) = make_uint4(h4, h5, h6, h7);
        *(uint4*)(smem + bo + OFF_BL + sa)  = make_uint4(l0, l1, l2, l3);
        *(uint4*)(smem + bo + OFF_BL + sbo) = make_uint4(l4, l5, l6, l7);
    };

    auto slice = [&](uint32_t bb, int s) {
        uint32_t ahf[2][4], bhf[NTG][4], alf[2][4];
        LDSM4(ahf[0], bb + OFF_AH + aAddr[0][s]);
        LDSM4(ahf[1], bb + OFF_AH + aAddr[1][s]);
        #pragma unroll
        for (int nt = 0; nt < NTG; nt++) LDSM4(bhf[nt], bb + OFF_BH + bAddr[nt][s]);
        #pragma unroll
        for (int mt = 0; mt < 2; mt++)
            #pragma unroll
            for (int nt = 0; nt < NTG; nt++) {
                mma16816(acc[mt][nt * 2],     ahf[mt], bhf[nt][0], bhf[nt][1]);
                mma16816(acc[mt][nt * 2 + 1], ahf[mt], bhf[nt][2], bhf[nt][3]);
            }
        LDSM4(alf[0], bb + OFF_AL + aAddr[0][s]);
        LDSM4(alf[1], bb + OFF_AL + aAddr[1][s]);
        #pragma unroll
        for (int mt = 0; mt < 2; mt++)
            #pragma unroll
            for (int nt = 0; nt < NTG; nt++) {
                mma16816(acc[mt][nt * 2],     alf[mt], bhf[nt][0], bhf[nt][1]);
                mma16816(acc[mt][nt * 2 + 1], alf[mt], bhf[nt][2], bhf[nt][3]);
            }
        #pragma unroll
        for (int nt = 0; nt < NTG; nt++) LDSM4(bhf[nt], bb + OFF_BL + bAddr[nt][s]);
        #pragma unroll
        for (int mt = 0; mt < 2; mt++)
            #pragma unroll
            for (int nt = 0; nt < NTG; nt++) {
                mma16816(acc[mt][nt * 2],     ahf[mt], bhf[nt][0], bhf[nt][1]);
                mma16816(acc[mt][nt * 2 + 1], ahf[mt], bhf[nt][2], bhf[nt][3]);
            }
    };

    // ---- prologue: chunk 0 -> buf0 ----
    issueA(0, 0);
    loadB(0, 0); stsB(0, 0);
    if (NTG == 4) { loadB(1, 0); stsB(1, 0); }
    CP_WAIT(0);
    __syncthreads();

    for (int c = 0; c < C; c++) {
        const uint32_t bb = sb + (uint32_t)buf * BUF_BYTES;
        const uint32_t nbo = (uint32_t)(buf ^ 1) * BUF_BYTES;
        const bool more = (c + 1 < C);

        if (more) { issueA(nbo, (c + 1) * 32); loadB(0, (c + 1) * 32); }
        slice(bb, 0);
        if (more) { stsB(0, nbo); if (NTG == 4) loadB(1, (c + 1) * 32); }
        slice(bb, 1);
        if (more) {
            if (NTG == 4) stsB(1, nbo);
            CP_WAIT(0);
            __syncthreads();
            buf ^= 1;
        }
    }

    // ---- epilogue ----
    float* Dp = D + dBS * blockIdx.y + (long long)mtb * 64 * Nglob + ntb * NTILE;
    const float* cvp = cv ? cv + (long long)blockIdx.y * N_ + ntb * NTILE : nullptr;
    #pragma unroll
    for (int mt = 0; mt < 2; mt++) {
        const int rr0 = wm + mt * 16 + (lane >> 2);
        const int rr1 = rr0 + 8;
        const float bv0 = bias ? bias[mtb * 64 + rr0] : 0.0f;
        const float bv1 = bias ? bias[mtb * 64 + rr1] : 0.0f;
        const float rv0 = rv ? rv[mtb * 64 + rr0] : 0.0f;
        const float rv1 = rv ? rv[mtb * 64 + rr1] : 0.0f;
        #pragma unroll
        for (int j = 0; j < 2 * NTG; j++) {
            const int cc = wn + j * 8 + 2 * (lane & 3);
            float c0 = 0.0f, c1 = 0.0f;
            if (cvp) { c0 = cvp[cc]; c1 = cvp[cc + 1]; }
            float v0 = acc[mt][j][0] * outScale + bv0 + rv0 * c0;
            float v1 = acc[mt][j][1] * outScale + bv0 + rv0 * c1;
            float v2 = acc[mt][j][2] * outScale + bv1 + rv1 * c0;
            float v3 = acc[mt][j][3] * outScale + bv1 + rv1 * c1;
            if (relu) {
                v0 = fmaxf(v0, 0.0f); v1 = fmaxf(v1, 0.0f);
                v2 = fmaxf(v2, 0.0f); v3 = fmaxf(v3, 0.0f);
            }
            *(float2*)(Dp + (long long)rr0 * Nglob + cc) = make_float2(v0, v1);
            *(float2*)(Dp + (long long)rr1 * Nglob + cc) = make_float2(v2, v3);
        }
    }
}

// ---------------------------------------------------------------------------
// finalize (unchanged)
// ---------------------------------------------------------------------------
__global__ void finalize_kernel(const float* __restrict__ hT,
                                const float* __restrict__ W_out,
                                const float* __restrict__ b_out,
                                float* __restrict__ out)
{
    const int b = blockIdx.x, tid = threadIdx.x;
    const float* base = hT + (long long)b * DIM_ * N_;
    const float4* r0 = (const float4*)(base + (long long)tid * N_);
    const float4* r1 = (const float4*)(base + (long long)(tid + 256) * N_);
    float s0 = 0.0f, s1 = 0.0f;
    #pragma unroll 8
    for (int j = 0; j < 32; j++) {
        float4 a = r0[j]; s0 += (a.x + a.y) + (a.z + a.w);
        float4 c = r1[j]; s1 += (c.x + c.y) + (c.z + c.w);
    }
    const float g0 = s0 * (1.0f / (float)N_);
    const float g1 = s1 * (1.0f / (float)N_);
    out[B_ + b * DIM_ + tid]       = g0;
    out[B_ + b * DIM_ + tid + 256] = g1;

    __shared__ float red[256];
    red[tid] = g0 * W_out[tid] + g1 * W_out[tid + 256];
    __syncthreads();
    for (int s = 128; s > 0; s >>= 1) {
        if (tid < s) red[tid] += red[tid + s];
        __syncthreads();
    }
    if (tid == 0) out[b] = red[0] + b_out[0];
}

// ---------------------------------------------------------------------------
// launch
// ---------------------------------------------------------------------------
extern "C" void kernel_launch(void* const* d_in, const int* in_sizes, int n_in,
                              void* d_out, int out_size)
{
    const float* adj      = (const float*)d_in[0];
    // d_in[1] = hidden (unused by forward)
    const float* node     = (const float*)d_in[2];
    const float* W_embed  = (const float*)d_in[3];
    const float* b_embed  = (const float*)d_in[4];
    const float* W_layers = (const float*)d_in[5];
    const float* b_layers = (const float*)d_in[6];
    const float* W_out    = (const float*)d_in[7];
    const float* b_out    = (const float*)d_in[8];
    float* out = (float*)d_out;

    float *hT, *t, *rs, *nodeT, *q, *we1p, *be1;
    __half *wh, *wl, *ah, *al, *we1h, *we1l;
    cudaGetSymbolAddress((void**)&hT,    g_hT);
    cudaGetSymbolAddress((void**)&t,     g_t);
    cudaGetSymbolAddress((void**)&wh,    g_wh);
    cudaGetSymbolAddress((void**)&wl,    g_wl);
    cudaGetSymbolAddress((void**)&ah,    g_ah);
    cudaGetSymbolAddress((void**)&al,    g_al);
    cudaGetSymbolAddress((void**)&rs,    g_rs);
    cudaGetSymbolAddress((void**)&nodeT, g_nodeT);
    cudaGetSymbolAddress((void**)&q,     g_q);
    cudaGetSymbolAddress((void**)&we1h,  g_we1h);
    cudaGetSymbolAddress((void**)&we1l,  g_we1l);
    cudaGetSymbolAddress((void**)&we1p,  g_we1p);
    cudaGetSymbolAddress((void**)&be1,   g_be1);

    cudaFuncSetAttribute(tgemm<4>, cudaFuncAttributeMaxDynamicSharedMemorySize, SMEM_BYTES);
    cudaFuncSetAttribute(tgemm<2>, cudaFuncAttributeMaxDynamicSharedMemorySize, SMEM_BYTES);

    // ---- prep ----
    asum_split_kernel<<<(B_ * N_ * N_ / 4) / 256, 256>>>(adj, ah, al, rs);
    wsplit_kernel<<<WSZ / 256, 256>>>(W_layers, W_embed, wh, wl);
    nodet_kernel<<<(B_ * NA_ * N_) / 256, 256>>>(node, nodeT);
    we1part_kernel<<<1024, 256>>>(W_embed, W_layers, we1p);
    we1red_kernel<<<(DIM_ * NA_) / 256, 256>>>(we1p, we1h, we1l);
    be1_kernel<<<64, 256>>>(b_embed, W_layers, be1);

    const float S  = 1.0f / 64.0f;
    const float iS = 64.0f;

    // ---- iteration 1 (algebraically collapsed) ----
    // G1: q[b][128][64] = M[b] @ node[b]   (K=128; mtiles=2, NTILE=64)
    tgemm<2><<<dim3(2, B_), 128, SMEM_BYTES>>>(
        ah, al, (long long)N_ * N_,
        nodeT, (long long)NA_ * N_,
        q, (long long)N_ * NA_,
        nullptr, N_, NA_, /*ntiles=*/1, /*relu=*/0, 1.0f, 1.0f,
        nullptr, nullptr);
    // G2: hT[b][512][128] = relu(We1T @ q[b]^T + rs⊗be1 + b1)  (K=64; mtiles=8)
    tgemm<4><<<dim3(8, B_), 128, SMEM_BYTES>>>(
        we1h, we1l, 0LL,
        q, (long long)N_ * NA_,
        hT, (long long)DIM_ * N_,
        b_layers, NA_, N_, /*ntiles=*/1, /*relu=*/1, 1.0f, 1.0f,
        be1, rs);

    // ---- iterations 2..3 ----
    for (int i = 1; i < NIT_; i++) {
        // t[b][128x512] = M[b] @ hT[b]^T   (K=128; mtiles=2, ntiles=4)
        tgemm<4><<<dim3(8, B_), 128, SMEM_BYTES>>>(
            ah, al, (long long)N_ * N_,
            hT, (long long)DIM_ * N_,
            t, (long long)N_ * DIM_,
            nullptr, N_, DIM_, /*ntiles=*/4, /*relu=*/0, S, iS,
            nullptr, nullptr);
        // hT[b][512x128] = relu(WT_i @ t[b]^T + b_i)   (K=512; mtiles=8)
        tgemm<4><<<dim3(8, B_), 128, SMEM_BYTES>>>(
            wh + (long long)i * LSZ, wl + (long long)i * LSZ, 0LL,
            t, (long long)N_ * DIM_,
            hT, (long long)DIM_ * N_,
            b_layers + i * DIM_, DIM_, N_, /*ntiles=*/1, /*relu=*/1, S, iS,
            nullptr, nullptr);
    }

    finalize_kernel<<<B_, 256>>>(hT, W_out, b_out, out);
}

// round 16
// speedup vs baseline: 1.1725x; 1.1725x over previous
#include <cuda_runtime.h>
#include <cuda_fp16.h>
#include <cstdint>

// Problem constants
#define B_    256
#define N_    128
#define EB_   5
#define NA_   64
#define DIM_  512
#define NIT_  3
#define MROWS (B_ * N_)
#define LSZ   (DIM_ * DIM_)
#define WSZ   (NIT_ * LSZ + DIM_ * NA_)

// Scratch (static device globals)
__device__ __align__(128) float  g_hT[B_ * DIM_ * N_];   // [B][512][128] hidden (transposed)
__device__ __align__(128) float  g_t [B_ * N_ * DIM_];   // [B][128][512] M@h
__device__ __align__(128) __half g_wh[WSZ];              // wT pre-split hi (layers 1,2 used)
__device__ __align__(128) __half g_wl[WSZ];
__device__ __align__(128) __half g_ah[B_ * N_ * N_];     // M = Σedges + I, hi
__device__ __align__(128) __half g_al[B_ * N_ * N_];     //                 lo
__device__ __align__(128) float  g_rs[MROWS];            // rowsums of M
__device__ __align__(128) float  g_nodeT[B_ * NA_ * N_]; // [B][64][128] node^T
__device__ __align__(128) float  g_q[B_ * N_ * NA_];     // [B][128][64] M@node
__device__ __align__(128) __half g_we1h[DIM_ * NA_];     // (We@W1)^T [512][64] hi
__device__ __align__(128) __half g_we1l[DIM_ * NA_];     //                     lo
__device__ __align__(128) float  g_we1p[8 * DIM_ * NA_]; // split-K partials
__device__ __align__(128) float  g_be1[DIM_];            // be@W1

// ---------------------------------------------------------------------------
// helpers
// ---------------------------------------------------------------------------
__device__ __forceinline__ void split2u(float a0, float a1, uint32_t& hi, uint32_t& lo) {
    __half2 h = __floats2half2_rn(a0, a1);
    float2  f = __half22float2(h);
    __half2 l = __floats2half2_rn(a0 - f.x, a1 - f.y);
    hi = *reinterpret_cast<uint32_t*>(&h);
    lo = *reinterpret_cast<uint32_t*>(&l);
}
__device__ __forceinline__ uint32_t smem_u32(const void* p) {
    uint32_t a;
    asm("{ .reg .u64 t; cvta.to.shared.u64 t, %1; cvt.u32.u64 %0, t; }" : "=r"(a) : "l"(p));
    return a;
}
__device__ __forceinline__ void cpasync16(uint32_t s, const void* g) {
    asm volatile("cp.async.cg.shared.global [%0], [%1], 16;" :: "r"(s), "l"(g));
}
#define CP_COMMIT() asm volatile("cp.async.commit_group;" ::: "memory")
#define CP_WAIT(n)  asm volatile("cp.async.wait_group %0;" :: "n"(n) : "memory")

#define LDSM4(r, addr) \
    asm volatile("ldmatrix.sync.aligned.m8n8.x4.shared.b16 {%0,%1,%2,%3}, [%4];" \
        : "=r"((r)[0]), "=r"((r)[1]), "=r"((r)[2]), "=r"((r)[3]) : "r"(addr))

__device__ __forceinline__ void mma16816(float* c, const uint32_t* a,
                                         uint32_t b0, uint32_t b1) {
    asm volatile(
        "mma.sync.aligned.m16n8k16.row.col.f32.f16.f16.f32 "
        "{%0,%1,%2,%3}, {%4,%5,%6,%7}, {%8,%9}, {%0,%1,%2,%3};"
        : "+f"(c[0]), "+f"(c[1]), "+f"(c[2]), "+f"(c[3])
        : "r"(a[0]), "r"(a[1]), "r"(a[2]), "r"(a[3]), "r"(b0), "r"(b1));
}

// swizzled byte offset inside one [rows][64B] tile
__device__ __forceinline__ uint32_t swz(int r, int kh) {
    return (uint32_t)(r * 64) + (uint32_t)((kh ^ ((r >> 1) & 3)) << 4);
}

// ---------------------------------------------------------------------------
// Prep kernels
// ---------------------------------------------------------------------------
// M = Σedges + I, split to half hi/lo; warp-reduced rowsums -> rs
__global__ void asum_split_kernel(const float* __restrict__ adj,
                                  __half* __restrict__ ah, __half* __restrict__ al,
                                  float* __restrict__ rs) {
    int g = blockIdx.x * 256 + threadIdx.x;            // over B*N*N/4, exact
    const float4* p = (const float4*)adj + (long long)g * 5;
    float4 f0 = p[0], f1 = p[1], f2 = p[2], f3 = p[3], f4 = p[4];
    float4 o;
    o.x = (f0.y + f0.z) + (f0.w + f1.x);
    o.y = (f1.z + f1.w) + (f2.x + f2.y);
    o.z = (f2.w + f3.x) + (f3.y + f3.z);
    o.w = (f4.x + f4.y) + (f4.z + f4.w);
    int i = g * 4;
    #pragma unroll
    for (int j = 0; j < 4; j++) {
        int nm = (i + j) & (N_ * N_ - 1);
        if ((nm >> 7) == (nm & 127)) (&o.x)[j] += 1.0f;   // +I (folds residual)
    }
    uint32_t h0, l0, h1, l1;
    split2u(o.x, o.y, h0, l0);
    split2u(o.z, o.w, h1, l1);
    ((uint2*)ah)[g] = make_uint2(h0, h1);
    ((uint2*)al)[g] = make_uint2(l0, l1);
    float s = (o.x + o.y) + (o.z + o.w);
    #pragma unroll
    for (int off = 16; off; off >>= 1) s += __shfl_xor_sync(0xFFFFFFFFu, s, off);
    if ((threadIdx.x & 31) == 0) rs[g >> 5] = s;
}

// transpose + split ONLY layers 1..NIT-1 (layer 0 is fused into we1; embed unused)
__global__ void wsplit_kernel(const float* __restrict__ W_layers,
                              __half* __restrict__ wh, __half* __restrict__ wl) {
    int i = blockIdx.x * 256 + threadIdx.x + LSZ;      // over [LSZ, NIT*LSZ)
    int l = i / LSZ, j = i % LSZ;
    int c = j / DIM_, r = j % DIM_;
    float v = W_layers[l * LSZ + r * DIM_ + c];
    __half h = __float2half_rn(v);
    wh[i] = h;
    wl[i] = __float2half_rn(v - __half2float(h));
}

// node^T: nodeT[b][na][m] = node[b][m][na]
__global__ void nodet_kernel(const float* __restrict__ node, float* __restrict__ nodeT) {
    int i = blockIdx.x * 256 + threadIdx.x;            // over B*64*128
    int b = i >> 13, j = i & 8191, na = j >> 7, m = j & 127;
    nodeT[i] = node[(b << 13) + (m << 6) + na];
}

// 8-way split-K partials of We@W1, 2 outputs/thread (independent FMA chains)
__global__ void we1part_kernel(const float* __restrict__ We, const float* __restrict__ W1,
                               float* __restrict__ we1p) {
    int blk = blockIdx.x;                              // 512 blocks
    int ks  = blk >> 6;                                // 0..7
    int i0  = ((blk & 63) * 256 + threadIdx.x) * 2;    // na*512 + d (even)
    int na = i0 >> 9, d = i0 & 511;
    float s0 = 0.0f, s1 = 0.0f;
    const float* wer = We + na * DIM_ + ks * 64;
    const float* w1r = W1 + (long long)(ks * 64) * DIM_ + d;
    #pragma unroll 8
    for (int k = 0; k < 64; k++) {
        float w = wer[k];
        s0 += w * w1r[(long long)k * DIM_];
        s1 += w * w1r[(long long)k * DIM_ + 1];
    }
    *(float2*)&we1p[ks * (DIM_ * NA_) + i0] = make_float2(s0, s1);
}

// reduce partials + split, transposed to [d][na]
__global__ void we1red_kernel(const float* __restrict__ we1p,
                              __half* __restrict__ weh, __half* __restrict__ wel) {
    int i = blockIdx.x * 256 + threadIdx.x;            // na*512 + d
    float s = 0.0f;
    #pragma unroll
    for (int ks = 0; ks < 8; ks++) s += we1p[ks * (DIM_ * NA_) + i];
    int na = i >> 9, d = i & 511;
    __half h = __float2half_rn(s);
    weh[d * NA_ + na] = h;
    wel[d * NA_ + na] = __float2half_rn(s - __half2float(h));
}

// be1[d] = Σ_k be[k] W1[k,d]  (warp-split-K, 64 blocks x 8 outputs)
__global__ void be1_kernel(const float* __restrict__ be, const float* __restrict__ W1,
                           float* __restrict__ be1) {
    int d = blockIdx.x * 8 + (threadIdx.x >> 5);
    int lane = threadIdx.x & 31;
    float s = 0.0f;
    #pragma unroll
    for (int j = 0; j < 16; j++) {
        int k = lane + 32 * j;
        s += be[k] * W1[(long long)k * DIM_ + d];
    }
    #pragma unroll
    for (int off = 16; off; off >>= 1) s += __shfl_xor_sync(0xFFFFFFFFu, s, off);
    if (lane == 0) be1[d] = s;
}

// ---------------------------------------------------------------------------
// 3xFP16-split tensor GEMM (round-14 proven config, verbatim):
//   D = A@B^T; A pre-split half hi/lo (cp.async double buffer);
//   B fp32, split in-kernel (reg prefetch + STS.128); fp32 D output.
//   v = acc*outScale + bias[row] + rv[row]*cv[col]; optional relu.
// NTG=4 -> 128x128 CTA tile; NTG=2 -> 128x64.
// 256 threads, 8 warps (4m x 2n); 2 CTAs/SM; K-chunk 32.
// ---------------------------------------------------------------------------
#define OFF_AH 0
#define OFF_AL 8192
#define OFF_BH 16384
#define OFF_BL 24576
#define BUF_BYTES  32768
#define SMEM_BYTES 65536

template<int NTG>
__global__ __launch_bounds__(256, 2)
void tgemm(const __half* __restrict__ Ah, const __half* __restrict__ Al, long long aBS,
           const float* __restrict__ Bm, long long bBS,
           float* __restrict__ D, long long dBS,
           const float* __restrict__ bias,
           int K, int Nglob, int ntiles, int relu,
           float bScale, float outScale,
           const float* __restrict__ rv, const float* __restrict__ cv)
{
    extern __shared__ char smem[];
    const uint32_t sb = smem_u32(smem);
    constexpr int NTILE = 32 * NTG;

    const int tid  = threadIdx.x;
    const int lane = tid & 31;
    const int warp = tid >> 5;             // 0..7
    const int mtb  = blockIdx.x / ntiles;
    const int ntb  = blockIdx.x % ntiles;
    const int wm   = (warp >> 1) * 32;
    const int wn   = (warp & 1) * (NTILE / 2);

    const __half* Aph = Ah + aBS * blockIdx.y + (long long)mtb * 128 * K;
    const __half* Apl = Al + aBS * blockIdx.y + (long long)mtb * 128 * K;
    const float*  Bp  = Bm + bBS * blockIdx.y + (long long)ntb * NTILE * K;

    const int lr = tid >> 2;               // 0..63
    const int sk = tid & 3;
    const uint32_t so0 = swz(lr, sk);
    const uint32_t so1 = swz(lr + 64, sk);
    const long long go0 = (long long)lr * K + sk * 8;
    const long long go1 = (long long)(lr + 64) * K + sk * 8;

    const int lane8 = lane & 7;
    const int rA0   = ((lane >> 3) & 1) * 8 + lane8;
    const int khA   = lane >> 4;
    const int rB0   = ((lane >> 4) & 1) * 8 + lane8;
    const int khB   = (lane >> 3) & 1;

    uint32_t aAddr[2][2], bAddr[NTG][2];
    #pragma unroll
    for (int mt = 0; mt < 2; mt++) {
        const int r = wm + mt * 16 + rA0;
        #pragma unroll
        for (int s = 0; s < 2; s++) aAddr[mt][s] = swz(r, s * 2 + khA);
    }
    #pragma unroll
    for (int nt = 0; nt < NTG; nt++) {
        const int r = wn + nt * 16 + rB0;
        #pragma unroll
        for (int s = 0; s < 2; s++) bAddr[nt][s] = swz(r, s * 2 + khB);
    }

    float acc[2][2 * NTG][4];
    #pragma unroll
    for (int i = 0; i < 2; i++)
        #pragma unroll
        for (int j = 0; j < 2 * NTG; j++)
            #pragma unroll
            for (int q = 0; q < 4; q++) acc[i][j][q] = 0.0f;

    const int C = K >> 5;
    int buf = 0;
    float4 b00, b01, b10, b11;

    auto slice = [&](uint32_t bb, int s) {
        uint32_t ahf[2][4], bhf[NTG][4], alf[2][4];
        LDSM4(ahf[0], bb + OFF_AH + aAddr[0][s]);
        LDSM4(ahf[1], bb + OFF_AH + aAddr[1][s]);
        #pragma unroll
        for (int nt = 0; nt < NTG; nt++) LDSM4(bhf[nt], bb + OFF_BH + bAddr[nt][s]);
        #pragma unroll
        for (int mt = 0; mt < 2; mt++)
            #pragma unroll
            for (int nt = 0; nt < NTG; nt++) {
                mma16816(acc[mt][nt * 2],     ahf[mt], bhf[nt][0], bhf[nt][1]);
                mma16816(acc[mt][nt * 2 + 1], ahf[mt], bhf[nt][2], bhf[nt][3]);
            }
        LDSM4(alf[0], bb + OFF_AL + aAddr[0][s]);
        LDSM4(alf[1], bb + OFF_AL + aAddr[1][s]);
        #pragma unroll
        for (int mt = 0; mt < 2; mt++)
            #pragma unroll
            for (int nt = 0; nt < NTG; nt++) {
                mma16816(acc[mt][nt * 2],     alf[mt], bhf[nt][0], bhf[nt][1]);
                mma16816(acc[mt][nt * 2 + 1], alf[mt], bhf[nt][2], bhf[nt][3]);
            }
        #pragma unroll
        for (int nt = 0; nt < NTG; nt++) LDSM4(bhf[nt], bb + OFF_BL + bAddr[nt][s]);
        #pragma unroll
        for (int mt = 0; mt < 2; mt++)
            #pragma unroll
            for (int nt = 0; nt < NTG; nt++) {
                mma16816(acc[mt][nt * 2],     ahf[mt], bhf[nt][0], bhf[nt][1]);
                mma16816(acc[mt][nt * 2 + 1], ahf[mt], bhf[nt][2], bhf[nt][3]);
            }
    };

    auto stsB = [&](uint32_t bo) {
        uint32_t h0, h1, h2, h3, l0, l1, l2, l3;
        split2u(b00.x * bScale, b00.y * bScale, h0, l0);
        split2u(b00.z * bScale, b00.w * bScale, h1, l1);
        split2u(b01.x * bScale, b01.y * bScale, h2, l2);
        split2u(b01.z * bScale, b01.w * bScale, h3, l3);
        *(uint4*)(smem + bo + OFF_BH + so0) = make_uint4(h0, h1, h2, h3);
        *(uint4*)(smem + bo + OFF_BL + so0) = make_uint4(l0, l1, l2, l3);
        if (NTG == 4) {
            split2u(b10.x * bScale, b10.y * bScale, h0, l0);
            split2u(b10.z * bScale, b10.w * bScale, h1, l1);
            split2u(b11.x * bScale, b11.y * bScale, h2, l2);
            split2u(b11.z * bScale, b11.w * bScale, h3, l3);
            *(uint4*)(smem + bo + OFF_BH + so1) = make_uint4(h0, h1, h2, h3);
            *(uint4*)(smem + bo + OFF_BL + so1) = make_uint4(l0, l1, l2, l3);
        }
    };

    // prologue: chunk 0 -> buf0
    cpasync16(sb + OFF_AH + so0, Aph + go0);
    cpasync16(sb + OFF_AH + so1, Aph + go1);
    cpasync16(sb + OFF_AL + so0, Apl + go0);
    cpasync16(sb + OFF_AL + so1, Apl + go1);
    CP_COMMIT();
    b00 = *(const float4*)(Bp + go0);
    b01 = *(const float4*)(Bp + go0 + 4);
    if (NTG == 4) {
        b10 = *(const float4*)(Bp + go1);
        b11 = *(const float4*)(Bp + go1 + 4);
    }
    stsB(0);
    CP_WAIT(0);
    __syncthreads();

    for (int c = 0; c < C; c++) {
        const uint32_t bb = sb + (uint32_t)buf * BUF_BYTES;
        const uint32_t nb = (uint32_t)(buf ^ 1) * BUF_BYTES;
        const bool more = (c + 1 < C);

        if (more) {
            const int g = (c + 1) * 32;
            cpasync16(sb + nb + OFF_AH + so0, Aph + go0 + g);
            cpasync16(sb + nb + OFF_AH + so1, Aph + go1 + g);
            cpasync16(sb + nb + OFF_AL + so0, Apl + go0 + g);
            cpasync16(sb + nb + OFF_AL + so1, Apl + go1 + g);
            CP_COMMIT();
            b00 = *(const float4*)(Bp + go0 + g);
            b01 = *(const float4*)(Bp + go0 + g + 4);
            if (NTG == 4) {
                b10 = *(const float4*)(Bp + go1 + g);
                b11 = *(const float4*)(Bp + go1 + g + 4);
            }
        }

        slice(bb, 0);
        if (more) stsB(nb);
        slice(bb, 1);

        if (more) {
            CP_WAIT(0);
            __syncthreads();
            buf ^= 1;
        }
    }

    // epilogue
    float* Dp = D + dBS * blockIdx.y + (long long)mtb * 128 * Nglob + ntb * NTILE;
    const float* cvp = cv ? cv + (long long)blockIdx.y * N_ + ntb * NTILE : nullptr;
    #pragma unroll
    for (int mt = 0; mt < 2; mt++) {
        const int rr0 = wm + mt * 16 + (lane >> 2);
        const int rr1 = rr0 + 8;
        const float bv0 = bias ? bias[mtb * 128 + rr0] : 0.0f;
        const float bv1 = bias ? bias[mtb * 128 + rr1] : 0.0f;
        const float rv0 = rv ? rv[mtb * 128 + rr0] : 0.0f;
        const float rv1 = rv ? rv[mtb * 128 + rr1] : 0.0f;
        #pragma unroll
        for (int j = 0; j < 2 * NTG; j++) {
            const int cc = wn + j * 8 + 2 * (lane & 3);
            float c0 = 0.0f, c1 = 0.0f;
            if (cvp) { c0 = cvp[cc]; c1 = cvp[cc + 1]; }
            float v0 = acc[mt][j][0] * outScale + bv0 + rv0 * c0;
            float v1 = acc[mt][j][1] * outScale + bv0 + rv0 * c1;
            float v2 = acc[mt][j][2] * outScale + bv1 + rv1 * c0;
            float v3 = acc[mt][j][3] * outScale + bv1 + rv1 * c1;
            if (relu) {
                v0 = fmaxf(v0, 0.0f); v1 = fmaxf(v1, 0.0f);
                v2 = fmaxf(v2, 0.0f); v3 = fmaxf(v3, 0.0f);
            }
            *(float2*)(Dp + (long long)rr0 * Nglob + cc) = make_float2(v0, v1);
            *(float2*)(Dp + (long long)rr1 * Nglob + cc) = make_float2(v2, v3);
        }
    }
}

// ---------------------------------------------------------------------------
// finalize: graph_repr[b] = mean_n hT[b][d][n];  logit = repr @ W_out + b_out
// out = [ logit(256) | graph_repr(256*512) ]
// ---------------------------------------------------------------------------
__global__ void finalize_kernel(const float* __restrict__ hT,
                                const float* __restrict__ W_out,
                                const float* __restrict__ b_out,
                                float* __restrict__ out)
{
    const int b = blockIdx.x, tid = threadIdx.x;
    const float* base = hT + (long long)b * DIM_ * N_;
    const float4* r0 = (const float4*)(base + (long long)tid * N_);
    const float4* r1 = (const float4*)(base + (long long)(tid + 256) * N_);
    float s0 = 0.0f, s1 = 0.0f;
    #pragma unroll 8
    for (int j = 0; j < 32; j++) {
        float4 a = r0[j]; s0 += (a.x + a.y) + (a.z + a.w);
        float4 c = r1[j]; s1 += (c.x + c.y) + (c.z + c.w);
    }
    const float g0 = s0 * (1.0f / (float)N_);
    const float g1 = s1 * (1.0f / (float)N_);
    out[B_ + b * DIM_ + tid]       = g0;
    out[B_ + b * DIM_ + tid + 256] = g1;

    __shared__ float red[256];
    red[tid] = g0 * W_out[tid] + g1 * W_out[tid + 256];
    __syncthreads();
    for (int s = 128; s > 0; s >>= 1) {
        if (tid < s) red[tid] += red[tid + s];
        __syncthreads();
    }
    if (tid == 0) out[b] = red[0] + b_out[0];
}

// ---------------------------------------------------------------------------
// launch
// ---------------------------------------------------------------------------
extern "C" void kernel_launch(void* const* d_in, const int* in_sizes, int n_in,
                              void* d_out, int out_size)
{
    const float* adj      = (const float*)d_in[0];
    // d_in[1] = hidden (unused by forward)
    const float* node     = (const float*)d_in[2];
    const float* W_embed  = (const float*)d_in[3];
    const float* b_embed  = (const float*)d_in[4];
    const float* W_layers = (const float*)d_in[5];
    const float* b_layers = (const float*)d_in[6];
    const float* W_out    = (const float*)d_in[7];
    const float* b_out    = (const float*)d_in[8];
    float* out = (float*)d_out;

    float *hT, *t, *rs, *nodeT, *q, *we1p, *be1;
    __half *wh, *wl, *ah, *al, *we1h, *we1l;
    cudaGetSymbolAddress((void**)&hT,    g_hT);
    cudaGetSymbolAddress((void**)&t,     g_t);
    cudaGetSymbolAddress((void**)&wh,    g_wh);
    cudaGetSymbolAddress((void**)&wl,    g_wl);
    cudaGetSymbolAddress((void**)&ah,    g_ah);
    cudaGetSymbolAddress((void**)&al,    g_al);
    cudaGetSymbolAddress((void**)&rs,    g_rs);
    cudaGetSymbolAddress((void**)&nodeT, g_nodeT);
    cudaGetSymbolAddress((void**)&q,     g_q);
    cudaGetSymbolAddress((void**)&we1h,  g_we1h);
    cudaGetSymbolAddress((void**)&we1l,  g_we1l);
    cudaGetSymbolAddress((void**)&we1p,  g_we1p);
    cudaGetSymbolAddress((void**)&be1,   g_be1);

    cudaFuncSetAttribute(tgemm<4>, cudaFuncAttributeMaxDynamicSharedMemorySize, SMEM_BYTES);
    cudaFuncSetAttribute(tgemm<2>, cudaFuncAttributeMaxDynamicSharedMemorySize, SMEM_BYTES);

    // ---- prep ----
    asum_split_kernel<<<(B_ * N_ * N_ / 4) / 256, 256>>>(adj, ah, al, rs);
    wsplit_kernel<<<((NIT_ - 1) * LSZ) / 256, 256>>>(W_layers, wh, wl);
    nodet_kernel<<<(B_ * NA_ * N_) / 256, 256>>>(node, nodeT);
    we1part_kernel<<<512, 256>>>(W_embed, W_layers, we1p);
    we1red_kernel<<<(DIM_ * NA_) / 256, 256>>>(we1p, we1h, we1l);
    be1_kernel<<<64, 256>>>(b_embed, W_layers, be1);

    const float S  = 1.0f / 64.0f;
    const float iS = 64.0f;

    // ---- iteration 1 (algebraically collapsed) ----
    // G1: q[b][128][64] = M[b] @ node[b]          (K=128, N=64)
    tgemm<2><<<dim3(1, B_), 256, SMEM_BYTES>>>(
        ah, al, (long long)N_ * N_,
        nodeT, (long long)NA_ * N_,
        q, (long long)N_ * NA_,
        nullptr, N_, NA_, /*ntiles=*/1, /*relu=*/0, 1.0f, 1.0f,
        nullptr, nullptr);
    // G2: hT[b][512][128] = relu(We1T @ q[b]^T + rs⊗be1 + b1)   (K=64)
    tgemm<4><<<dim3(4, B_), 256, SMEM_BYTES>>>(
        we1h, we1l, 0LL,
        q, (long long)N_ * NA_,
        hT, (long long)DIM_ * N_,
        b_layers, NA_, N_, /*ntiles=*/1, /*relu=*/1, 1.0f, 1.0f,
        be1, rs);

    // ---- iterations 2..3 (proven path) ----
    for (int i = 1; i < NIT_; i++) {
        tgemm<4><<<dim3(4, B_), 256, SMEM_BYTES>>>(
            ah, al, (long long)N_ * N_,
            hT, (long long)DIM_ * N_,
            t, (long long)N_ * DIM_,
            nullptr, N_, DIM_, /*ntiles=*/4, /*relu=*/0, S, iS,
            nullptr, nullptr);
        tgemm<4><<<dim3(4, B_), 256, SMEM_BYTES>>>(
            wh + (long long)i * LSZ, wl + (long long)i * LSZ, 0LL,
            t, (long long)N_ * DIM_,
            hT, (long long)DIM_ * N_,
            b_layers + i * DIM_, DIM_, N_, /*ntiles=*/1, /*relu=*/1, S, iS,
            nullptr, nullptr);
    }

    finalize_kernel<<<B_, 256>>>(hT, W_out, b_out, out);
}

// round 17
// speedup vs baseline: 1.2355x; 1.0537x over previous
#include <cuda_runtime.h>
#include <cuda_fp16.h>
#include <cstdint>

// Problem constants
#define B_    256
#define N_    128
#define EB_   5
#define NA_   64
#define DIM_  512
#define NIT_  3
#define MROWS (B_ * N_)
#define LSZ   (DIM_ * DIM_)
#define WSZ   (NIT_ * LSZ + DIM_ * NA_)

// Scratch (static device globals)
__device__ __align__(128) float  g_hT[B_ * DIM_ * N_];   // [B][512][128] hidden (transposed)
__device__ __align__(128) float  g_t [B_ * N_ * DIM_];   // [B][128][512] M@h
__device__ __align__(128) __half g_wh[WSZ];              // wT pre-split hi (layers 1,2 used)
__device__ __align__(128) __half g_wl[WSZ];
__device__ __align__(128) __half g_ah[B_ * N_ * N_];     // M = Σedges + I, hi
__device__ __align__(128) __half g_al[B_ * N_ * N_];     //                 lo
__device__ __align__(128) float  g_rs[MROWS];            // rowsums of M
__device__ __align__(128) float  g_nodeT[B_ * NA_ * N_]; // [B][64][128] node^T
__device__ __align__(128) float  g_q[B_ * N_ * NA_];     // [B][128][64] M@node
__device__ __align__(128) __half g_we1h[DIM_ * NA_];     // (We@W1)^T [512][64] hi
__device__ __align__(128) __half g_we1l[DIM_ * NA_];     //                     lo
__device__ __align__(128) float  g_we1p[8 * DIM_ * NA_]; // split-K partials
__device__ __align__(128) float  g_be1[DIM_];            // be@W1

// ---------------------------------------------------------------------------
// helpers
// ---------------------------------------------------------------------------
__device__ __forceinline__ void split2u(float a0, float a1, uint32_t& hi, uint32_t& lo) {
    __half2 h = __floats2half2_rn(a0, a1);
    float2  f = __half22float2(h);
    __half2 l = __floats2half2_rn(a0 - f.x, a1 - f.y);
    hi = *reinterpret_cast<uint32_t*>(&h);
    lo = *reinterpret_cast<uint32_t*>(&l);
}
__device__ __forceinline__ uint32_t cvt2u(float a0, float a1) {
    __half2 h = __floats2half2_rn(a0, a1);
    return *reinterpret_cast<uint32_t*>(&h);
}
__device__ __forceinline__ uint32_t smem_u32(const void* p) {
    uint32_t a;
    asm("{ .reg .u64 t; cvta.to.shared.u64 t, %1; cvt.u32.u64 %0, t; }" : "=r"(a) : "l"(p));
    return a;
}
__device__ __forceinline__ void cpasync16(uint32_t s, const void* g) {
    asm volatile("cp.async.cg.shared.global [%0], [%1], 16;" :: "r"(s), "l"(g));
}
#define CP_COMMIT() asm volatile("cp.async.commit_group;" ::: "memory")
#define CP_WAIT(n)  asm volatile("cp.async.wait_group %0;" :: "n"(n) : "memory")

#define LDSM4(r, addr) \
    asm volatile("ldmatrix.sync.aligned.m8n8.x4.shared.b16 {%0,%1,%2,%3}, [%4];" \
        : "=r"((r)[0]), "=r"((r)[1]), "=r"((r)[2]), "=r"((r)[3]) : "r"(addr))

__device__ __forceinline__ void mma16816(float* c, const uint32_t* a,
                                         uint32_t b0, uint32_t b1) {
    asm volatile(
        "mma.sync.aligned.m16n8k16.row.col.f32.f16.f16.f32 "
        "{%0,%1,%2,%3}, {%4,%5,%6,%7}, {%8,%9}, {%0,%1,%2,%3};"
        : "+f"(c[0]), "+f"(c[1]), "+f"(c[2]), "+f"(c[3])
        : "r"(a[0]), "r"(a[1]), "r"(a[2]), "r"(a[3]), "r"(b0), "r"(b1));
}

// swizzled byte offset inside one [rows][64B] tile
__device__ __forceinline__ uint32_t swz(int r, int kh) {
    return (uint32_t)(r * 64) + (uint32_t)((kh ^ ((r >> 1) & 3)) << 4);
}

// ---------------------------------------------------------------------------
// Prep kernels (unchanged from round 16)
// ---------------------------------------------------------------------------
__global__ void asum_split_kernel(const float* __restrict__ adj,
                                  __half* __restrict__ ah, __half* __restrict__ al,
                                  float* __restrict__ rs) {
    int g = blockIdx.x * 256 + threadIdx.x;            // over B*N*N/4, exact
    const float4* p = (const float4*)adj + (long long)g * 5;
    float4 f0 = p[0], f1 = p[1], f2 = p[2], f3 = p[3], f4 = p[4];
    float4 o;
    o.x = (f0.y + f0.z) + (f0.w + f1.x);
    o.y = (f1.z + f1.w) + (f2.x + f2.y);
    o.z = (f2.w + f3.x) + (f3.y + f3.z);
    o.w = (f4.x + f4.y) + (f4.z + f4.w);
    int i = g * 4;
    #pragma unroll
    for (int j = 0; j < 4; j++) {
        int nm = (i + j) & (N_ * N_ - 1);
        if ((nm >> 7) == (nm & 127)) (&o.x)[j] += 1.0f;   // +I (folds residual)
    }
    uint32_t h0, l0, h1, l1;
    split2u(o.x, o.y, h0, l0);
    split2u(o.z, o.w, h1, l1);
    ((uint2*)ah)[g] = make_uint2(h0, h1);
    ((uint2*)al)[g] = make_uint2(l0, l1);
    float s = (o.x + o.y) + (o.z + o.w);
    #pragma unroll
    for (int off = 16; off; off >>= 1) s += __shfl_xor_sync(0xFFFFFFFFu, s, off);
    if ((threadIdx.x & 31) == 0) rs[g >> 5] = s;
}

// transpose + split ONLY layers 1..NIT-1 (layer 0 fused into we1; embed unused)
__global__ void wsplit_kernel(const float* __restrict__ W_layers,
                              __half* __restrict__ wh, __half* __restrict__ wl) {
    int i = blockIdx.x * 256 + threadIdx.x + LSZ;      // over [LSZ, NIT*LSZ)
    int l = i / LSZ, j = i % LSZ;
    int c = j / DIM_, r = j % DIM_;
    float v = W_layers[l * LSZ + r * DIM_ + c];
    __half h = __float2half_rn(v);
    wh[i] = h;
    wl[i] = __float2half_rn(v - __half2float(h));
}

__global__ void nodet_kernel(const float* __restrict__ node, float* __restrict__ nodeT) {
    int i = blockIdx.x * 256 + threadIdx.x;            // over B*64*128
    int b = i >> 13, j = i & 8191, na = j >> 7, m = j & 127;
    nodeT[i] = node[(b << 13) + (m << 6) + na];
}

__global__ void we1part_kernel(const float* __restrict__ We, const float* __restrict__ W1,
                               float* __restrict__ we1p) {
    int blk = blockIdx.x;                              // 512 blocks
    int ks  = blk >> 6;                                // 0..7
    int i0  = ((blk & 63) * 256 + threadIdx.x) * 2;    // na*512 + d (even)
    int na = i0 >> 9, d = i0 & 511;
    float s0 = 0.0f, s1 = 0.0f;
    const float* wer = We + na * DIM_ + ks * 64;
    const float* w1r = W1 + (long long)(ks * 64) * DIM_ + d;
    #pragma unroll 8
    for (int k = 0; k < 64; k++) {
        float w = wer[k];
        s0 += w * w1r[(long long)k * DIM_];
        s1 += w * w1r[(long long)k * DIM_ + 1];
    }
    *(float2*)&we1p[ks * (DIM_ * NA_) + i0] = make_float2(s0, s1);
}

__global__ void we1red_kernel(const float* __restrict__ we1p,
                              __half* __restrict__ weh, __half* __restrict__ wel) {
    int i = blockIdx.x * 256 + threadIdx.x;            // na*512 + d
    float s = 0.0f;
    #pragma unroll
    for (int ks = 0; ks < 8; ks++) s += we1p[ks * (DIM_ * NA_) + i];
    int na = i >> 9, d = i & 511;
    __half h = __float2half_rn(s);
    weh[d * NA_ + na] = h;
    wel[d * NA_ + na] = __float2half_rn(s - __half2float(h));
}

__global__ void be1_kernel(const float* __restrict__ be, const float* __restrict__ W1,
                           float* __restrict__ be1) {
    int d = blockIdx.x * 8 + (threadIdx.x >> 5);
    int lane = threadIdx.x & 31;
    float s = 0.0f;
    #pragma unroll
    for (int j = 0; j < 16; j++) {
        int k = lane + 32 * j;
        s += be[k] * W1[(long long)k * DIM_ + d];
    }
    #pragma unroll
    for (int off = 16; off; off >>= 1) s += __shfl_xor_sync(0xFFFFFFFFu, s, off);
    if (lane == 0) be1[d] = s;
}

// ---------------------------------------------------------------------------
// FP16-split tensor GEMM:  D = A@B^T
//   TERMS=3: acc = Ah*Bh + Al*Bh + Ah*Bl   (full 3-term split)
//   TERMS=1: acc = Ah*Bh                   (pure fp16 — ONLY valid when both
//            operands are non-negative: no cancellation bounds the error)
//   A pre-split half hi/lo (cp.async double buffer; AL skipped for TERMS=1);
//   B fp32 split in-kernel (BL skipped for TERMS=1); fp32 D output.
//   v = acc*outScale + bias[row] + rv[row]*cv[col]; optional relu.
// NTG=4 -> 128x128 CTA tile; NTG=2 -> 128x64.
// 256 threads, 8 warps (4m x 2n); 2 CTAs/SM; K-chunk 32.
// ---------------------------------------------------------------------------
#define OFF_AH 0
#define OFF_AL 8192
#define OFF_BH 16384
#define OFF_BL 24576
#define BUF_BYTES  32768
#define SMEM_BYTES 65536

template<int NTG, int TERMS>
__global__ __launch_bounds__(256, 2)
void tgemm(const __half* __restrict__ Ah, const __half* __restrict__ Al, long long aBS,
           const float* __restrict__ Bm, long long bBS,
           float* __restrict__ D, long long dBS,
           const float* __restrict__ bias,
           int K, int Nglob, int ntiles, int relu,
           float bScale, float outScale,
           const float* __restrict__ rv, const float* __restrict__ cv)
{
    extern __shared__ char smem[];
    const uint32_t sb = smem_u32(smem);
    constexpr int NTILE = 32 * NTG;

    const int tid  = threadIdx.x;
    const int lane = tid & 31;
    const int warp = tid >> 5;             // 0..7
    const int mtb  = blockIdx.x / ntiles;
    const int ntb  = blockIdx.x % ntiles;
    const int wm   = (warp >> 1) * 32;
    const int wn   = (warp & 1) * (NTILE / 2);

    const __half* Aph = Ah + aBS * blockIdx.y + (long long)mtb * 128 * K;
    const __half* Apl = Al + aBS * blockIdx.y + (long long)mtb * 128 * K;
    const float*  Bp  = Bm + bBS * blockIdx.y + (long long)ntb * NTILE * K;

    const int lr = tid >> 2;               // 0..63
    const int sk = tid & 3;
    const uint32_t so0 = swz(lr, sk);
    const uint32_t so1 = swz(lr + 64, sk);
    const long long go0 = (long long)lr * K + sk * 8;
    const long long go1 = (long long)(lr + 64) * K + sk * 8;

    const int lane8 = lane & 7;
    const int rA0   = ((lane >> 3) & 1) * 8 + lane8;
    const int khA   = lane >> 4;
    const int rB0   = ((lane >> 4) & 1) * 8 + lane8;
    const int khB   = (lane >> 3) & 1;

    uint32_t aAddr[2][2], bAddr[NTG][2];
    #pragma unroll
    for (int mt = 0; mt < 2; mt++) {
        const int r = wm + mt * 16 + rA0;
        #pragma unroll
        for (int s = 0; s < 2; s++) aAddr[mt][s] = swz(r, s * 2 + khA);
    }
    #pragma unroll
    for (int nt = 0; nt < NTG; nt++) {
        const int r = wn + nt * 16 + rB0;
        #pragma unroll
        for (int s = 0; s < 2; s++) bAddr[nt][s] = swz(r, s * 2 + khB);
    }

    float acc[2][2 * NTG][4];
    #pragma unroll
    for (int i = 0; i < 2; i++)
        #pragma unroll
        for (int j = 0; j < 2 * NTG; j++)
            #pragma unroll
            for (int q = 0; q < 4; q++) acc[i][j][q] = 0.0f;

    const int C = K >> 5;
    int buf = 0;
    float4 b00, b01, b10, b11;

    auto slice = [&](uint32_t bb, int s) {
        uint32_t ahf[2][4], bhf[NTG][4];
        LDSM4(ahf[0], bb + OFF_AH + aAddr[0][s]);
        LDSM4(ahf[1], bb + OFF_AH + aAddr[1][s]);
        #pragma unroll
        for (int nt = 0; nt < NTG; nt++) LDSM4(bhf[nt], bb + OFF_BH + bAddr[nt][s]);
        // term 1: Ah * Bh
        #pragma unroll
        for (int mt = 0; mt < 2; mt++)
            #pragma unroll
            for (int nt = 0; nt < NTG; nt++) {
                mma16816(acc[mt][nt * 2],     ahf[mt], bhf[nt][0], bhf[nt][1]);
                mma16816(acc[mt][nt * 2 + 1], ahf[mt], bhf[nt][2], bhf[nt][3]);
            }
        if (TERMS == 3) {
            // term 2: Al * Bh
            uint32_t alf[2][4];
            LDSM4(alf[0], bb + OFF_AL + aAddr[0][s]);
            LDSM4(alf[1], bb + OFF_AL + aAddr[1][s]);
            #pragma unroll
            for (int mt = 0; mt < 2; mt++)
                #pragma unroll
                for (int nt = 0; nt < NTG; nt++) {
                    mma16816(acc[mt][nt * 2],     alf[mt], bhf[nt][0], bhf[nt][1]);
                    mma16816(acc[mt][nt * 2 + 1], alf[mt], bhf[nt][2], bhf[nt][3]);
                }
            // term 3: Ah * Bl
            #pragma unroll
            for (int nt = 0; nt < NTG; nt++) LDSM4(bhf[nt], bb + OFF_BL + bAddr[nt][s]);
            #pragma unroll
            for (int mt = 0; mt < 2; mt++)
                #pragma unroll
                for (int nt = 0; nt < NTG; nt++) {
                    mma16816(acc[mt][nt * 2],     ahf[mt], bhf[nt][0], bhf[nt][1]);
                    mma16816(acc[mt][nt * 2 + 1], ahf[mt], bhf[nt][2], bhf[nt][3]);
                }
        }
    };

    auto stsB = [&](uint32_t bo) {
        if (TERMS == 3) {
            uint32_t h0, h1, h2, h3, l0, l1, l2, l3;
            split2u(b00.x * bScale, b00.y * bScale, h0, l0);
            split2u(b00.z * bScale, b00.w * bScale, h1, l1);
            split2u(b01.x * bScale, b01.y * bScale, h2, l2);
            split2u(b01.z * bScale, b01.w * bScale, h3, l3);
            *(uint4*)(smem + bo + OFF_BH + so0) = make_uint4(h0, h1, h2, h3);
            *(uint4*)(smem + bo + OFF_BL + so0) = make_uint4(l0, l1, l2, l3);
            if (NTG == 4) {
                split2u(b10.x * bScale, b10.y * bScale, h0, l0);
                split2u(b10.z * bScale, b10.w * bScale, h1, l1);
                split2u(b11.x * bScale, b11.y * bScale, h2, l2);
                split2u(b11.z * bScale, b11.w * bScale, h3, l3);
                *(uint4*)(smem + bo + OFF_BH + so1) = make_uint4(h0, h1, h2, h3);
                *(uint4*)(smem + bo + OFF_BL + so1) = make_uint4(l0, l1, l2, l3);
            }
        } else {
            uint4 v;
            v.x = cvt2u(b00.x * bScale, b00.y * bScale);
            v.y = cvt2u(b00.z * bScale, b00.w * bScale);
            v.z = cvt2u(b01.x * bScale, b01.y * bScale);
            v.w = cvt2u(b01.z * bScale, b01.w * bScale);
            *(uint4*)(smem + bo + OFF_BH + so0) = v;
            if (NTG == 4) {
                v.x = cvt2u(b10.x * bScale, b10.y * bScale);
                v.y = cvt2u(b10.z * bScale, b10.w * bScale);
                v.z = cvt2u(b11.x * bScale, b11.y * bScale);
                v.w = cvt2u(b11.z * bScale, b11.w * bScale);
                *(uint4*)(smem + bo + OFF_BH + so1) = v;
            }
        }
    };

    auto issueA = [&](uint32_t bo, int g) {
        cpasync16(sb + bo + OFF_AH + so0, Aph + go0 + g);
        cpasync16(sb + bo + OFF_AH + so1, Aph + go1 + g);
        if (TERMS == 3) {
            cpasync16(sb + bo + OFF_AL + so0, Apl + go0 + g);
            cpasync16(sb + bo + OFF_AL + so1, Apl + go1 + g);
        }
        CP_COMMIT();
    };

    // prologue: chunk 0 -> buf0
    issueA(0, 0);
    b00 = *(const float4*)(Bp + go0);
    b01 = *(const float4*)(Bp + go0 + 4);
    if (NTG == 4) {
        b10 = *(const float4*)(Bp + go1);
        b11 = *(const float4*)(Bp + go1 + 4);
    }
    stsB(0);
    CP_WAIT(0);
    __syncthreads();

    for (int c = 0; c < C; c++) {
        const uint32_t bb = sb + (uint32_t)buf * BUF_BYTES;
        const uint32_t nb = (uint32_t)(buf ^ 1) * BUF_BYTES;
        const bool more = (c + 1 < C);

        if (more) {
            const int g = (c + 1) * 32;
            issueA(nb, g);
            b00 = *(const float4*)(Bp + go0 + g);
            b01 = *(const float4*)(Bp + go0 + g + 4);
            if (NTG == 4) {
                b10 = *(const float4*)(Bp + go1 + g);
                b11 = *(const float4*)(Bp + go1 + g + 4);
            }
        }

        slice(bb, 0);
        if (more) stsB(nb);
        slice(bb, 1);

        if (more) {
            CP_WAIT(0);
            __syncthreads();
            buf ^= 1;
        }
    }

    // epilogue
    float* Dp = D + dBS * blockIdx.y + (long long)mtb * 128 * Nglob + ntb * NTILE;
    const float* cvp = cv ? cv + (long long)blockIdx.y * N_ + ntb * NTILE : nullptr;
    #pragma unroll
    for (int mt = 0; mt < 2; mt++) {
        const int rr0 = wm + mt * 16 + (lane >> 2);
        const int rr1 = rr0 + 8;
        const float bv0 = bias ? bias[mtb * 128 + rr0] : 0.0f;
        const float bv1 = bias ? bias[mtb * 128 + rr1] : 0.0f;
        const float rv0 = rv ? rv[mtb * 128 + rr0] : 0.0f;
        const float rv1 = rv ? rv[mtb * 128 + rr1] : 0.0f;
        #pragma unroll
        for (int j = 0; j < 2 * NTG; j++) {
            const int cc = wn + j * 8 + 2 * (lane & 3);
            float c0 = 0.0f, c1 = 0.0f;
            if (cvp) { c0 = cvp[cc]; c1 = cvp[cc + 1]; }
            float v0 = acc[mt][j][0] * outScale + bv0 + rv0 * c0;
            float v1 = acc[mt][j][1] * outScale + bv0 + rv0 * c1;
            float v2 = acc[mt][j][2] * outScale + bv1 + rv1 * c0;
            float v3 = acc[mt][j][3] * outScale + bv1 + rv1 * c1;
            if (relu) {
                v0 = fmaxf(v0, 0.0f); v1 = fmaxf(v1, 0.0f);
                v2 = fmaxf(v2, 0.0f); v3 = fmaxf(v3, 0.0f);
            }
            *(float2*)(Dp + (long long)rr0 * Nglob + cc) = make_float2(v0, v1);
            *(float2*)(Dp + (long long)rr1 * Nglob + cc) = make_float2(v2, v3);
        }
    }
}

// ---------------------------------------------------------------------------
// finalize: graph_repr[b] = mean_n hT[b][d][n];  logit = repr @ W_out + b_out
// out = [ logit(256) | graph_repr(256*512) ]
// ---------------------------------------------------------------------------
__global__ void finalize_kernel(const float* __restrict__ hT,
                                const float* __restrict__ W_out,
                                const float* __restrict__ b_out,
                                float* __restrict__ out)
{
    const int b = blockIdx.x, tid = threadIdx.x;
    const float* base = hT + (long long)b * DIM_ * N_;
    const float4* r0 = (const float4*)(base + (long long)tid * N_);
    const float4* r1 = (const float4*)(base + (long long)(tid + 256) * N_);
    float s0 = 0.0f, s1 = 0.0f;
    #pragma unroll 8
    for (int j = 0; j < 32; j++) {
        float4 a = r0[j]; s0 += (a.x + a.y) + (a.z + a.w);
        float4 c = r1[j]; s1 += (c.x + c.y) + (c.z + c.w);
    }
    const float g0 = s0 * (1.0f / (float)N_);
    const float g1 = s1 * (1.0f / (float)N_);
    out[B_ + b * DIM_ + tid]       = g0;
    out[B_ + b * DIM_ + tid + 256] = g1;

    __shared__ float red[256];
    red[tid] = g0 * W_out[tid] + g1 * W_out[tid + 256];
    __syncthreads();
    for (int s = 128; s > 0; s >>= 1) {
        if (tid < s) red[tid] += red[tid + s];
        __syncthreads();
    }
    if (tid == 0) out[b] = red[0] + b_out[0];
}

// ---------------------------------------------------------------------------
// launch
// ---------------------------------------------------------------------------
extern "C" void kernel_launch(void* const* d_in, const int* in_sizes, int n_in,
                              void* d_out, int out_size)
{
    const float* adj      = (const float*)d_in[0];
    // d_in[1] = hidden (unused by forward)
    const float* node     = (const float*)d_in[2];
    const float* W_embed  = (const float*)d_in[3];
    const float* b_embed  = (const float*)d_in[4];
    const float* W_layers = (const float*)d_in[5];
    const float* b_layers = (const float*)d_in[6];
    const float* W_out    = (const float*)d_in[7];
    const float* b_out    = (const float*)d_in[8];
    float* out = (float*)d_out;

    float *hT, *t, *rs, *nodeT, *q, *we1p, *be1;
    __half *wh, *wl, *ah, *al, *we1h, *we1l;
    cudaGetSymbolAddress((void**)&hT,    g_hT);
    cudaGetSymbolAddress((void**)&t,     g_t);
    cudaGetSymbolAddress((void**)&wh,    g_wh);
    cudaGetSymbolAddress((void**)&wl,    g_wl);
    cudaGetSymbolAddress((void**)&ah,    g_ah);
    cudaGetSymbolAddress((void**)&al,    g_al);
    cudaGetSymbolAddress((void**)&rs,    g_rs);
    cudaGetSymbolAddress((void**)&nodeT, g_nodeT);
    cudaGetSymbolAddress((void**)&q,     g_q);
    cudaGetSymbolAddress((void**)&we1h,  g_we1h);
    cudaGetSymbolAddress((void**)&we1l,  g_we1l);
    cudaGetSymbolAddress((void**)&we1p,  g_we1p);
    cudaGetSymbolAddress((void**)&be1,   g_be1);

    cudaFuncSetAttribute(tgemm<4,3>, cudaFuncAttributeMaxDynamicSharedMemorySize, SMEM_BYTES);
    cudaFuncSetAttribute(tgemm<2,3>, cudaFuncAttributeMaxDynamicSharedMemorySize, SMEM_BYTES);
    cudaFuncSetAttribute(tgemm<4,1>, cudaFuncAttributeMaxDynamicSharedMemorySize, SMEM_BYTES);

    // ---- prep ----
    asum_split_kernel<<<(B_ * N_ * N_ / 4) / 256, 256>>>(adj, ah, al, rs);
    wsplit_kernel<<<((NIT_ - 1) * LSZ) / 256, 256>>>(W_layers, wh, wl);
    nodet_kernel<<<(B_ * NA_ * N_) / 256, 256>>>(node, nodeT);
    we1part_kernel<<<512, 256>>>(W_embed, W_layers, we1p);
    we1red_kernel<<<(DIM_ * NA_) / 256, 256>>>(we1p, we1h, we1l);
    be1_kernel<<<64, 256>>>(b_embed, W_layers, be1);

    const float S  = 1.0f / 64.0f;
    const float iS = 64.0f;

    // ---- iteration 1 (algebraically collapsed; signed operands -> 3-term) ----
    // G1: q[b][128][64] = M[b] @ node[b]          (K=128, N=64)
    tgemm<2,3><<<dim3(1, B_), 256, SMEM_BYTES>>>(
        ah, al, (long long)N_ * N_,
        nodeT, (long long)NA_ * N_,
        q, (long long)N_ * NA_,
        nullptr, N_, NA_, /*ntiles=*/1, /*relu=*/0, 1.0f, 1.0f,
        nullptr, nullptr);
    // G2: hT[b][512][128] = relu(We1T @ q[b]^T + rs⊗be1 + b1)   (K=64)
    tgemm<4,3><<<dim3(4, B_), 256, SMEM_BYTES>>>(
        we1h, we1l, 0LL,
        q, (long long)N_ * NA_,
        hT, (long long)DIM_ * N_,
        b_layers, NA_, N_, /*ntiles=*/1, /*relu=*/1, 1.0f, 1.0f,
        be1, rs);

    // ---- iterations 2..3 ----
    for (int i = 1; i < NIT_; i++) {
        // agg: t = M @ h  — both operands NON-NEGATIVE (M >= 0, h post-relu)
        // -> no cancellation -> pure fp16 (1-term) is precision-safe.
        tgemm<4,1><<<dim3(4, B_), 256, SMEM_BYTES>>>(
            ah, al, (long long)N_ * N_,
            hT, (long long)DIM_ * N_,
            t, (long long)N_ * DIM_,
            nullptr, N_, DIM_, /*ntiles=*/4, /*relu=*/0, S, iS,
            nullptr, nullptr);
        // layer: signed weights -> full 3-term split.
        tgemm<4,3><<<dim3(4, B_), 256, SMEM_BYTES>>>(
            wh + (long long)i * LSZ, wl + (long long)i * LSZ, 0LL,
            t, (long long)N_ * DIM_,
            hT, (long long)DIM_ * N_,
            b_layers + i * DIM_, DIM_, N_, /*ntiles=*/1, /*relu=*/1, S, iS,
            nullptr, nullptr);
    }

    finalize_kernel<<<B_, 256>>>(hT, W_out, b_out, out);
}